// round 11
// baseline (speedup 1.0000x reference)
#include <cuda_runtime.h>

// SWT level-1 (db2, norm=True) along channel axis with periodic wrap.
// x:   [B=8, C=64, H=128, W=128] f32
// out: [B=8, 2C=128, H=128, W=128] f32  (cA in [0,64), cD in [64,128))
//
// cA[c] = lo0*x[c+2] + lo1*x[c+1] + lo2*x[c] + lo3*x[c-1]   (mod 64)
// cD[c] = hi0*x[c+2] + hi1*x[c+1] + hi2*x[c] + hi3*x[c-1]
//
// R10: CHUNK=4 sliding window with prefetch-2 (5 live planes, MLP_p1~5,
// stores interleaved with remaining loads), __launch_bounds__(256,7) for
// 7 CTAs/SM (regs<=36) -> two even waves at grid=2048. __stcs kept.

#define HW4 4096  // (128*128)/4 float4 per channel plane
#define CHUNK 4

__global__ __launch_bounds__(256, 7)
void swt_db2_kernel(const float4* __restrict__ x, float4* __restrict__ out) {
    const float INV_SQRT2 = 0.70710678118654752440f;
    const float lo0 = -0.12940952255092145f * INV_SQRT2;  // * x[c+2]
    const float lo1 =  0.22414386804185735f * INV_SQRT2;  // * x[c+1]
    const float lo2 =  0.83651630373746900f * INV_SQRT2;  // * x[c]
    const float lo3 =  0.48296291314469025f * INV_SQRT2;  // * x[c-1]
    const float hi0 = -0.48296291314469025f * INV_SQRT2;
    const float hi1 =  0.83651630373746900f * INV_SQRT2;
    const float hi2 = -0.22414386804185735f * INV_SQRT2;
    const float hi3 = -0.12940952255092145f * INV_SQRT2;

    int t = blockIdx.x * blockDim.x + threadIdx.x;   // 0 .. 524287
    int s     = t & 4095;          // float4 index within HxW plane
    int chunk = (t >> 12) & 15;    // which 4-channel chunk
    int b     = t >> 16;           // batch
    int c0    = chunk << 2;        // first output channel of this chunk

    const float4* xin = x   + ((size_t)b << 18) + s;                     // b*64*4096
    float4*       oA  = out + ((size_t)b << 19) + (size_t)c0 * HW4 + s;  // b*128*4096
    float4*       oD  = oA + (size_t)64 * HW4;

    // Prologue: window planes c0-1..c0+1 plus two prefetched (c0+2, c0+3).
    // c0 max = 60, so c0+1..c0+3 need wrap only via &63 (c0+3 <= 63, no wrap).
    float4 w0 = xin[(size_t)((c0 + 63) & 63) * HW4];
    float4 w1 = xin[(size_t)c0 * HW4];
    float4 w2 = xin[(size_t)(c0 + 1) * HW4];
    float4 p  = xin[(size_t)(c0 + 2) * HW4];
    float4 q  = xin[(size_t)(c0 + 3) * HW4];

#pragma unroll
    for (int i = 0; i < CHUNK; ++i) {
        float4 w3 = p;
        p = q;
        if (i < CHUNK - 2)  // peel: exactly 7 loads total, none wasted
            q = xin[(size_t)((c0 + i + 4) & 63) * HW4];

        float4 A, D;
        A.x = fmaf(lo0, w3.x, fmaf(lo1, w2.x, fmaf(lo2, w1.x, lo3 * w0.x)));
        A.y = fmaf(lo0, w3.y, fmaf(lo1, w2.y, fmaf(lo2, w1.y, lo3 * w0.y)));
        A.z = fmaf(lo0, w3.z, fmaf(lo1, w2.z, fmaf(lo2, w1.z, lo3 * w0.z)));
        A.w = fmaf(lo0, w3.w, fmaf(lo1, w2.w, fmaf(lo2, w1.w, lo3 * w0.w)));
        D.x = fmaf(hi0, w3.x, fmaf(hi1, w2.x, fmaf(hi2, w1.x, hi3 * w0.x)));
        D.y = fmaf(hi0, w3.y, fmaf(hi1, w2.y, fmaf(hi2, w1.y, hi3 * w0.y)));
        D.z = fmaf(hi0, w3.z, fmaf(hi1, w2.z, fmaf(hi2, w1.z, hi3 * w0.z)));
        D.w = fmaf(hi0, w3.w, fmaf(hi1, w2.w, fmaf(hi2, w1.w, hi3 * w0.w)));

        // Streaming stores: output is write-once; evict-first protects input in L2.
        __stcs(&oA[(size_t)i * HW4], A);
        __stcs(&oD[(size_t)i * HW4], D);

        w0 = w1; w1 = w2; w2 = w3;
    }
}

extern "C" void kernel_launch(void* const* d_in, const int* in_sizes, int n_in,
                              void* d_out, int out_size) {
    const float4* x = (const float4*)d_in[0];
    float4* out = (float4*)d_out;
    // 8 batches * 16 chunks * 4096 spatial float4 = 524288 threads
    swt_db2_kernel<<<2048, 256>>>(x, out);
}